// round 5
// baseline (speedup 1.0000x reference)
#include <cuda_runtime.h>
#include <cstdint>

#define EMB     128     // per-node embedding dim
#define N_IN    256     // 2*EMB
#define HID     64
#define HID2    (HID/2) // hidden dim in f32x2 pairs
#define TPB     128
#define EPT     2       // edges per thread
#define EPB     (TPB * EPT)   // 256 edges per block
#define N_NODES 100000

// Set by detect_dtype_kernel: 1 if edge_index buffer is int64, 0 if int32.
__device__ int g_ei_is_i64;

__global__ void detect_dtype_kernel(const int* __restrict__ ei)
{
    // int64 indices < 2^31 => every odd 32-bit word is 0.
    // int32 indices: odd words are themselves indices (0 with p~1e-5 each).
    g_ei_is_i64 = (ei[1] == 0 && ei[3] == 0 && ei[5] == 0 && ei[7] == 0) ? 1 : 0;
}

// Packed dual-FMA: d = a*b + c on two fp32 lanes (Blackwell f32x2 pipe).
__device__ __forceinline__ void fma2(unsigned long long& d,
                                     unsigned long long a,
                                     unsigned long long b,
                                     unsigned long long c)
{
    asm("fma.rn.f32x2 %0, %1, %2, %3;" : "=l"(d) : "l"(a), "l"(b), "l"(c));
}

__device__ __forceinline__ unsigned long long bcast2(float x)
{
    unsigned long long r;
    unsigned int xi = __float_as_uint(x);
    asm("mov.b64 %0, {%1, %2};" : "=l"(r) : "r"(xi), "r"(xi));
    return r;
}

__device__ __forceinline__ void unpack2(unsigned long long p, float& lo, float& hi)
{
    unsigned int l, h;
    asm("mov.b64 {%0, %1}, %2;" : "=r"(l), "=r"(h) : "l"(p));
    lo = __uint_as_float(l);
    hi = __uint_as_float(h);
}

// Accumulate one 128-float half (src or tgt) of the edge feature into the
// packed hidden accumulators for two edges. W rows come from smem via
// LDS.128 broadcast (read as ulonglong2 -> two f32x2 operands each).
__device__ __forceinline__ void mlp_accum_half(
    const float4* __restrict__ r1,      // edge-1 node row (32 float4)
    const float4* __restrict__ r2,      // edge-2 node row
    const float*  __restrict__ Wbase,   // smem W1 rows for this half [128][HID]
    unsigned long long* __restrict__ acc1,   // [HID2] packed f32x2
    unsigned long long* __restrict__ acc2)
{
    float4 f1 = r1[0];
    float4 f2 = r2[0];
    #pragma unroll 1
    for (int c = 0; c < EMB / 4; c++) {
        // Prefetch next iteration's gather while this body runs (last iter
        // re-reads the current element from L1 — harmless, branch-free).
        int cn = min(c + 1, EMB / 4 - 1);
        float4 n1 = r1[cn];
        float4 n2 = r2[cn];

        float x1v[4] = {f1.x, f1.y, f1.z, f1.w};
        float x2v[4] = {f2.x, f2.y, f2.z, f2.w};
        #pragma unroll
        for (int kk = 0; kk < 4; kk++) {
            const ulonglong2* wv = reinterpret_cast<const ulonglong2*>(
                Wbase + (c * 4 + kk) * HID);
            unsigned long long x1 = bcast2(x1v[kk]);
            unsigned long long x2 = bcast2(x2v[kk]);
            #pragma unroll
            for (int j = 0; j < HID2 / 2; j++) {   // 16 LDS.128 -> 32 f32x2 words
                ulonglong2 w = wv[j];              // broadcast, conflict-free
                fma2(acc1[j * 2 + 0], x1, w.x, acc1[j * 2 + 0]);
                fma2(acc1[j * 2 + 1], x1, w.y, acc1[j * 2 + 1]);
                fma2(acc2[j * 2 + 0], x2, w.x, acc2[j * 2 + 0]);
                fma2(acc2[j * 2 + 1], x2, w.y, acc2[j * 2 + 1]);
            }
        }
        f1 = n1;
        f2 = n2;
    }
}

__global__ __launch_bounds__(TPB)
void edge_mlp_kernel(const float* __restrict__ emb,
                     const int* __restrict__ ei,    // [2,E]; dtype per g_ei_is_i64
                     const float* __restrict__ W1,
                     const float* __restrict__ b1,
                     const float* __restrict__ W2,
                     const float* __restrict__ b2,
                     float* __restrict__ out,
                     int E)
{
    extern __shared__ float sm[];
    float* W1s = sm;                    // [256][64] = 64 KB
    float* b1s = sm + N_IN * HID;       // [64]
    float* W2s = b1s + HID;             // [64]

    // Stage weights into shared memory (vectorized)
    {
        const float4* src = reinterpret_cast<const float4*>(W1);
        float4*       dst = reinterpret_cast<float4*>(W1s);
        #pragma unroll 4
        for (int i = threadIdx.x; i < (N_IN * HID) / 4; i += TPB)
            dst[i] = src[i];
        if (threadIdx.x < HID) {
            b1s[threadIdx.x] = b1[threadIdx.x];
            W2s[threadIdx.x] = W2[threadIdx.x];
        }
    }
    float bias2 = b2[0];

    int e1i = blockIdx.x * EPB + threadIdx.x;
    int e2i = e1i + TPB;
    bool v1 = e1i < E;
    bool v2 = e2i < E;
    int e1 = v1 ? e1i : 0;   // clamp so OOB threads still do uniform (valid) work
    int e2 = v2 ? e2i : 0;

    int s1, t1, s2, t2;
    if (g_ei_is_i64) {                  // uniform branch, same for all threads
        const long long* ei64 = reinterpret_cast<const long long*>(ei);
        s1 = (int)ei64[e1];
        t1 = (int)ei64[E + e1];
        s2 = (int)ei64[e2];
        t2 = (int)ei64[E + e2];
    } else {
        s1 = ei[e1];
        t1 = ei[E + e1];
        s2 = ei[e2];
        t2 = ei[E + e2];
    }
    // Defensive clamp: never fault, even if the dtype guess is wrong —
    // a wrong rel_err + a timing + an ncu profile beats an illegal access.
    s1 = min(max(s1, 0), N_NODES - 1);
    t1 = min(max(t1, 0), N_NODES - 1);
    s2 = min(max(s2, 0), N_NODES - 1);
    t2 = min(max(t2, 0), N_NODES - 1);

    const float4* r1a = reinterpret_cast<const float4*>(emb + (size_t)s1 * EMB);
    const float4* r1b = reinterpret_cast<const float4*>(emb + (size_t)t1 * EMB);
    const float4* r2a = reinterpret_cast<const float4*>(emb + (size_t)s2 * EMB);
    const float4* r2b = reinterpret_cast<const float4*>(emb + (size_t)t2 * EMB);

    unsigned long long acc1[HID2], acc2[HID2];
    #pragma unroll
    for (int j = 0; j < HID2; j++) { acc1[j] = 0ULL; acc2[j] = 0ULL; }

    __syncthreads();   // W1s/b1s/W2s ready

    // Layer 1: src half (k = 0..127), then tgt half (k = 128..255)
    mlp_accum_half(r1a, r2a, W1s,             acc1, acc2);
    mlp_accum_half(r1b, r2b, W1s + EMB * HID, acc1, acc2);

    // Epilogue: bias + ReLU + layer 2 (unpack pairs, scalar in registers)
    float sc1 = 0.f, sc2 = 0.f;
    #pragma unroll
    for (int j = 0; j < HID2; j++) {
        float a1lo, a1hi, a2lo, a2hi;
        unpack2(acc1[j], a1lo, a1hi);
        unpack2(acc2[j], a2lo, a2hi);
        float b_lo = b1s[2 * j + 0], b_hi = b1s[2 * j + 1];
        float w_lo = W2s[2 * j + 0], w_hi = W2s[2 * j + 1];
        sc1 += fmaxf(a1lo + b_lo, 0.f) * w_lo;
        sc1 += fmaxf(a1hi + b_hi, 0.f) * w_hi;
        sc2 += fmaxf(a2lo + b_lo, 0.f) * w_lo;
        sc2 += fmaxf(a2hi + b_hi, 0.f) * w_hi;
    }
    if (v1) out[e1i] = sc1 + bias2;
    if (v2) out[e2i] = sc2 + bias2;
}

extern "C" void kernel_launch(void* const* d_in, const int* in_sizes, int n_in,
                              void* d_out, int out_size)
{
    const float* emb = (const float*)d_in[0];       // [100000,128] f32
    const int*   ei  = (const int*)d_in[1];         // [2,E] int32 OR int64
    const float* W1  = (const float*)d_in[2];       // [256,64]
    const float* b1  = (const float*)d_in[3];       // [64]
    const float* W2  = (const float*)d_in[4];       // [64,1]
    const float* b2  = (const float*)d_in[5];       // [1]
    float* out = (float*)d_out;
    int E = out_size;

    size_t smem = (size_t)(N_IN * HID + 2 * HID) * sizeof(float);  // ~66 KB
    cudaFuncSetAttribute(edge_mlp_kernel,
                         cudaFuncAttributeMaxDynamicSharedMemorySize, (int)smem);

    detect_dtype_kernel<<<1, 1>>>(ei);
    int grid = (E + EPB - 1) / EPB;
    edge_mlp_kernel<<<grid, TPB, smem>>>(emb, ei, W1, b1, W2, b2, out, E);
}

// round 14
// speedup vs baseline: 5.4752x; 5.4752x over previous
#include <cuda_runtime.h>
#include <cstdint>

#define EMB     128
#define N_IN    256
#define HID     64
#define HROW    128          // Htop[64] | Hbot[64] per node
#define N_NODES 100000
#define PC_TPB  256
#define EG_TPB  256
#define EG_GRID 592

// 51.2 MB scratch: per-node hidden pre-activations (static __device__ = allowed)
__device__ float g_H[(size_t)N_NODES * HROW];
__device__ int g_ei_is_i64;

__global__ void detect_dtype_kernel(const int* __restrict__ ei)
{
    // int64 indices < 2^31 => odd 32-bit words are 0; int32: p(all four zero) ~1e-20
    g_ei_is_i64 = (ei[1] == 0 && ei[3] == 0 && ei[5] == 0 && ei[7] == 0) ? 1 : 0;
}

// ---- packed f32x2 helpers (Blackwell dual-FMA pipe) ----
__device__ __forceinline__ void fma2(unsigned long long& d, unsigned long long a,
                                     unsigned long long b, unsigned long long c)
{
    asm("fma.rn.f32x2 %0, %1, %2, %3;" : "=l"(d) : "l"(a), "l"(b), "l"(c));
}
__device__ __forceinline__ unsigned long long bcast2(float x)
{
    unsigned long long r; unsigned int xi = __float_as_uint(x);
    asm("mov.b64 %0, {%1, %2};" : "=l"(r) : "r"(xi), "r"(xi));
    return r;
}
__device__ __forceinline__ unsigned long long pack2(float lo, float hi)
{
    unsigned long long r;
    asm("mov.b64 %0, {%1, %2};" : "=l"(r) : "r"(__float_as_uint(lo)), "r"(__float_as_uint(hi)));
    return r;
}
__device__ __forceinline__ void unpack2(unsigned long long p, float& lo, float& hi)
{
    unsigned int l, h;
    asm("mov.b64 {%0, %1}, %2;" : "=r"(l), "=r"(h) : "l"(p));
    lo = __uint_as_float(l); hi = __uint_as_float(h);
}

// ---- Phase 1: per-node hidden pre-activations ----
// Htop[n][j] = emb[n]·W1[0:128][j] + b1[j] ; Hbot[n][j] = emb[n]·W1[128:256][j]
__global__ __launch_bounds__(PC_TPB)
void precompute_kernel(const float* __restrict__ emb,
                       const float* __restrict__ W1,
                       const float* __restrict__ b1)
{
    extern __shared__ float sm[];
    float* W1s = sm;               // [256][64]
    float* b1s = sm + N_IN * HID;  // [64]
    {
        const float4* src = reinterpret_cast<const float4*>(W1);
        float4* dst = reinterpret_cast<float4*>(W1s);
        #pragma unroll 4
        for (int i = threadIdx.x; i < (N_IN * HID) / 4; i += PC_TPB)
            dst[i] = src[i];
        if (threadIdx.x < HID) b1s[threadIdx.x] = b1[threadIdx.x];
    }
    __syncthreads();

    int n = blockIdx.x * PC_TPB + threadIdx.x;
    bool valid = n < N_NODES;
    int nc = valid ? n : N_NODES - 1;
    const float4* row = reinterpret_cast<const float4*>(emb + (size_t)nc * EMB);

    #pragma unroll 1
    for (int half = 0; half < 2; half++) {
        unsigned long long acc[HID / 2];
        #pragma unroll
        for (int j = 0; j < HID / 2; j++)
            acc[j] = (half == 0) ? pack2(b1s[2 * j], b1s[2 * j + 1]) : 0ULL;

        #pragma unroll 1
        for (int c = 0; c < EMB / 4; c++) {
            float4 x = row[c];
            float xs[4] = {x.x, x.y, x.z, x.w};
            #pragma unroll
            for (int kk = 0; kk < 4; kk++) {
                const ulonglong2* wv = reinterpret_cast<const ulonglong2*>(
                    W1s + (half * EMB + c * 4 + kk) * HID);
                unsigned long long xb = bcast2(xs[kk]);
                #pragma unroll
                for (int j = 0; j < HID / 4; j++) {     // 16 LDS.128 broadcast
                    ulonglong2 w = wv[j];
                    fma2(acc[2 * j + 0], xb, w.x, acc[2 * j + 0]);
                    fma2(acc[2 * j + 1], xb, w.y, acc[2 * j + 1]);
                }
            }
        }
        if (valid) {
            float4* dst = reinterpret_cast<float4*>(g_H + (size_t)n * HROW + half * HID);
            #pragma unroll
            for (int j = 0; j < HID / 4; j++) {
                float4 o;
                unpack2(acc[2 * j + 0], o.x, o.y);
                unpack2(acc[2 * j + 1], o.z, o.w);
                dst[j] = o;
            }
        }
    }
}

// ---- Phase 2: per-edge score. Warp-cooperative: lane l owns hid {2l,2l+1}. ----
__global__ __launch_bounds__(EG_TPB)
void edge_kernel(const int* __restrict__ ei,
                 const float* __restrict__ W2,
                 const float* __restrict__ b2,
                 float* __restrict__ out,
                 int E)
{
    int lane = threadIdx.x & 31;
    int gwarp = (blockIdx.x * EG_TPB + threadIdx.x) >> 5;
    int nwarps = (EG_GRID * EG_TPB) >> 5;
    bool is64 = (g_ei_is_i64 != 0);

    float w2x = W2[2 * lane];
    float w2y = W2[2 * lane + 1];
    float b2v = b2[0];

    #pragma unroll 1
    for (int base = gwarp * 8; base < E; base += nwarps * 8) {
        // lanes 0-7: src ids of edges base..base+7; lanes 8-15: tgt ids
        int id = 0;
        if (lane < 16) {
            int e = min(base + (lane & 7), E - 1);
            int half = lane >> 3;
            if (is64) {
                id = (int)reinterpret_cast<const long long*>(ei)[(size_t)half * E + e];
            } else {
                id = ei[(size_t)half * E + e];
            }
            id = min(max(id, 0), N_NODES - 1);
        }

        // 16 independent L2-resident loads in flight
        float2 hs[8], ht[8];
        #pragma unroll
        for (int u = 0; u < 8; u++) {
            int s = __shfl_sync(0xffffffffu, id, u);
            int t = __shfl_sync(0xffffffffu, id, u + 8);
            hs[u] = *reinterpret_cast<const float2*>(g_H + (size_t)s * HROW + 2 * lane);
            ht[u] = *reinterpret_cast<const float2*>(g_H + (size_t)t * HROW + HID + 2 * lane);
        }

        float p[8];
        #pragma unroll
        for (int u = 0; u < 8; u++) {
            float v0 = fmaxf(hs[u].x + ht[u].x, 0.f);
            float v1 = fmaxf(hs[u].y + ht[u].y, 0.f);
            p[u] = fmaf(v0, w2x, v1 * w2y);
        }
        // butterfly-reduce all 8 partial sets simultaneously
        #pragma unroll
        for (int d = 16; d >= 1; d >>= 1) {
            #pragma unroll
            for (int u = 0; u < 8; u++)
                p[u] += __shfl_xor_sync(0xffffffffu, p[u], d);
        }
        // lanes 0-7 write the 8 scores (select chain avoids dynamic reg index)
        float r = p[0];
        #pragma unroll
        for (int u = 1; u < 8; u++) r = (lane == u) ? p[u] : r;
        if (lane < 8 && base + lane < E)
            out[base + lane] = r + b2v;
    }
}

extern "C" void kernel_launch(void* const* d_in, const int* in_sizes, int n_in,
                              void* d_out, int out_size)
{
    const float* emb = (const float*)d_in[0];   // [100000,128] f32
    const int*   ei  = (const int*)d_in[1];     // [2,E] int32 or int64
    const float* W1  = (const float*)d_in[2];   // [256,64]
    const float* b1  = (const float*)d_in[3];   // [64]
    const float* W2  = (const float*)d_in[4];   // [64,1]
    const float* b2  = (const float*)d_in[5];   // [1]
    float* out = (float*)d_out;
    int E = out_size;

    int pc_smem = (N_IN * HID + HID) * sizeof(float);   // ~65.8 KB
    cudaFuncSetAttribute(precompute_kernel,
                         cudaFuncAttributeMaxDynamicSharedMemorySize, pc_smem);

    detect_dtype_kernel<<<1, 1>>>(ei);
    int pc_grid = (N_NODES + PC_TPB - 1) / PC_TPB;      // 391
    precompute_kernel<<<pc_grid, PC_TPB, pc_smem>>>(emb, W1, b1);
    edge_kernel<<<EG_GRID, EG_TPB>>>(ei, W2, b2, out, E);
}